// round 17
// baseline (speedup 1.0000x reference)
#include <cuda_runtime.h>
#include <cuda_fp16.h>
#include <math.h>
#include <stdint.h>

#define B_   16
#define CC   512
#define C8   64
#define C2   256
#define LOC  4096
#define DOWN 1024
#define MTOT 65536

// ---------------------------------------------------------------------------
// Device scratch: unified fp16 planes (packed half2 u32, pairs along k)
// ---------------------------------------------------------------------------
__device__ float d_invs[4];
__device__ uint32_t d_xh   [MTOT * 256];
__device__ uint32_t d_xl   [MTOT * 256];
__device__ uint32_t d_wtpTh[128 * 256];
__device__ uint32_t d_wtpTl[128 * 256];
__device__ uint32_t d_wgTf [256 * 256];
__device__ uint32_t d_waTf [512 * 128];
__device__ uint32_t d_thh  [MTOT * 32];
__device__ uint32_t d_thl  [MTOT * 32];
__device__ uint32_t d_phh  [B_ * DOWN * 32];
__device__ uint32_t d_phl  [B_ * DOWN * 32];
__device__ uint32_t d_gTf  [B_ * C2 * 512];
__device__ uint32_t d_agf  [MTOT * 128];

// ---------------------------------------------------------------------------
// helpers
// ---------------------------------------------------------------------------
__device__ __forceinline__ uint32_t pack2h(float a, float b) {
    __half2 h = __floats2half2_rn(a, b);
    return *(uint32_t*)&h;
}
__device__ __forceinline__ void split2h(float a, float b, uint32_t& hi, uint32_t& lo) {
    float ha = __half2float(__float2half_rn(a));
    float hb = __half2float(__float2half_rn(b));
    hi = pack2h(ha, hb);
    lo = pack2h(a - ha, b - hb);
}
__device__ __forceinline__ void mma_f16(float4& d,
    uint32_t a0, uint32_t a1, uint32_t a2, uint32_t a3, uint32_t b0, uint32_t b1)
{
    asm volatile("mma.sync.aligned.m16n8k16.row.col.f32.f16.f16.f32 "
        "{%0,%1,%2,%3}, {%4,%5,%6,%7}, {%8,%9}, {%0,%1,%2,%3};"
        : "+f"(d.x), "+f"(d.y), "+f"(d.z), "+f"(d.w)
        : "r"(a0), "r"(a1), "r"(a2), "r"(a3), "r"(b0), "r"(b1));
}
__device__ __forceinline__ void mma_x3(float4& d,
    const uint32_t ah[4], const uint32_t al[4],
    uint32_t bh0, uint32_t bh1, uint32_t bl0, uint32_t bl1)
{
    mma_f16(d, ah[0], ah[1], ah[2], ah[3], bh0, bh1);
    mma_f16(d, ah[0], ah[1], ah[2], ah[3], bl0, bl1);
    mma_f16(d, al[0], al[1], al[2], al[3], bh0, bh1);
}
__device__ __forceinline__ void ldsm4(uint32_t r[4], uint32_t addr) {
    asm volatile("ldmatrix.sync.aligned.m8n8.x4.shared.b16 {%0,%1,%2,%3}, [%4];"
        : "=r"(r[0]), "=r"(r[1]), "=r"(r[2]), "=r"(r[3]) : "r"(addr));
}
__device__ __forceinline__ void cp16(uint32_t dst_saddr, const uint32_t* src) {
    asm volatile("cp.async.cg.shared.global [%0], [%1], 16;\n" :: "r"(dst_saddr), "l"(src));
}
__device__ __forceinline__ void cp_commit() {
    asm volatile("cp.async.commit_group;\n" ::: "memory");
}
__device__ __forceinline__ void cp_wait0() {
    asm volatile("cp.async.wait_group 0;\n" ::: "memory");
}
__device__ __forceinline__ void cp_wait1() {
    asm volatile("cp.async.wait_group 1;\n" ::: "memory");
}

// ---------------------------------------------------------------------------
// prep_all: blocks 0-3 spectral norms, 4-643 weights, 644+ x split
// ---------------------------------------------------------------------------
__global__ void prep_all(const float* __restrict__ x,
                         const float* __restrict__ kt, const float* __restrict__ ut,
                         const float* __restrict__ kp, const float* __restrict__ up,
                         const float* __restrict__ kg, const float* __restrict__ ug,
                         const float* __restrict__ ka, const float* __restrict__ ua,
                         uint32_t* __restrict__ xh,  uint32_t* __restrict__ xl,
                         uint32_t* __restrict__ tpTh, uint32_t* __restrict__ tpTl,
                         uint32_t* __restrict__ gTf,  uint32_t* __restrict__ aTf)
{
    __shared__ float us[512];
    __shared__ float v[512];
    __shared__ float red[256];
    const int t = threadIdx.x;
    const int blk = blockIdx.x;

    if (blk >= 644) {
        size_t idx = (size_t)(blk - 644) * 256 + t;
        const float4* p = (const float4*)(x + idx * 8);
        float4 v0 = p[0], v1 = p[1];
        uint32_t h0,l0,h1,l1,h2,l2,h3,l3;
        split2h(v0.x, v0.y, h0, l0); split2h(v0.z, v0.w, h1, l1);
        split2h(v1.x, v1.y, h2, l2); split2h(v1.z, v1.w, h3, l3);
        *(uint4*)&xh[idx * 4] = make_uint4(h0, h1, h2, h3);
        *(uint4*)&xl[idx * 4] = make_uint4(l0, l1, l2, l3);
        return;
    }
    if (blk >= 4) {
        int i = (blk - 4) * 256 + t;
        if (i < 32768) {
            int n = i >> 8, j = i & 255;
            float a, b;
            if (n < 64) { a = kt[(2*j)*64 + n];      b = kt[(2*j+1)*64 + n]; }
            else        { a = kp[(2*j)*64 + n - 64]; b = kp[(2*j+1)*64 + n - 64]; }
            uint32_t h, l; split2h(a, b, h, l);
            tpTh[i] = h; tpTl[i] = l;
        } else if (i < 98304) {
            int i2 = i - 32768; int n = i2 >> 8, j = i2 & 255;
            gTf[i2] = pack2h(kg[(2*j)*256 + n], kg[(2*j+1)*256 + n]);
        } else if (i < 163840) {
            int i2 = i - 98304; int n = i2 >> 7, j = i2 & 127;
            aTf[i2] = pack2h(ka[(2*j)*512 + n], ka[(2*j+1)*512 + n]);
        }
        return;
    }

    const float* W; const float* u; int Cin, Cout;
    switch (blk) {
        case 0:  W = kt; u = ut; Cin = 512; Cout = 64;  break;
        case 1:  W = kp; u = up; Cin = 512; Cout = 64;  break;
        case 2:  W = kg; u = ug; Cin = 512; Cout = 256; break;
        default: W = ka; u = ua; Cin = 256; Cout = 512; break;
    }
    for (int j = t; j < Cout; j += 256) us[j] = u[j];
    __syncthreads();
    for (int i = t; i < Cin; i += 256) {
        const float4* wr = (const float4*)(W + (size_t)i * Cout);
        float s = 0.f;
        for (int j = 0; j < Cout / 4; j++) {
            float4 w4 = wr[j];
            s += us[4*j]*w4.x + us[4*j+1]*w4.y + us[4*j+2]*w4.z + us[4*j+3]*w4.w;
        }
        v[i] = s;
    }
    __syncthreads();
    float ss = 0.f;
    for (int i = t; i < Cin; i += 256) ss += v[i] * v[i];
    red[t] = ss; __syncthreads();
    for (int o = 128; o; o >>= 1) { if (t < o) red[t] += red[t + o]; __syncthreads(); }
    float inv_vn = 1.0f / (sqrtf(red[0]) + 1e-12f);
    __syncthreads();
    float rr = 0.f;
    for (int j = t; j < Cout; j += 256) {
        float s = 0.f;
        for (int i = 0; i < Cin; i++) s += v[i] * W[(size_t)i * Cout + j];
        s *= inv_vn;
        rr += s * s;
    }
    red[t] = rr; __syncthreads();
    for (int o = 128; o; o >>= 1) { if (t < o) red[t] += red[t + o]; __syncthreads(); }
    if (t == 0) {
        float rn = red[0];
        d_invs[blk] = (sqrtf(rn) + 1e-12f) / rn;
    }
}

// ---------------------------------------------------------------------------
// fp16 x3 GEMM (theta/phi conv): unchanged
// ---------------------------------------------------------------------------
#define PLANE 2560
#define GEMM_SMEM (8 * PLANE * 4)

__global__ __launch_bounds__(256, 2)
void gemm_x3(const uint32_t* __restrict__ Ah, const uint32_t* __restrict__ Al,
             const uint32_t* __restrict__ Bh, const uint32_t* __restrict__ Bl,
             uint32_t* __restrict__ oph, uint32_t* __restrict__ opl,
             uint32_t* __restrict__ phh, uint32_t* __restrict__ phl, int KP)
{
    extern __shared__ uint32_t smg[];
    const uint32_t smb = (uint32_t)__cvta_generic_to_shared(smg);

    const int bm = blockIdx.y * 128;
    const int t = threadIdx.x;
    const int warp = t >> 5, lane = t & 31, g = lane >> 2, tg = lane & 3;
    const int wm = (warp >> 1) * 32, wn = (warp & 1) * 64;

    const int ar = (lane & 7) + ((lane >> 3) & 1) * 8;
    const int ak = (lane >> 4) * 4;
    const int br = (lane & 7) + (lane >> 4) * 8;
    const int bk = ((lane >> 3) & 1) * 4;
    uint32_t aoff[2], boff[4];
    #pragma unroll
    for (int mf = 0; mf < 2; mf++) aoff[mf] = ((wm + mf*16 + ar) * 20 + ak) * 4;
    #pragma unroll
    for (int p = 0; p < 4; p++)    boff[p]  = ((wn + p*16 + br) * 20 + bk) * 4;

    const int rs = t >> 1;
    const int hf = (t & 1) * 8;
    const int sidx = rs * 20 + hf;
    const uint32_t* pAh = Ah + (size_t)(bm + rs) * KP + hf;
    const uint32_t* pAl = Al + (size_t)(bm + rs) * KP + hf;
    const uint32_t* pBh = Bh + (size_t)rs * KP + hf;
    const uint32_t* pBl = Bl + (size_t)rs * KP + hf;

    float4 acc[2][8];
    #pragma unroll
    for (int i = 0; i < 2; i++)
        #pragma unroll
        for (int j = 0; j < 8; j++) acc[i][j] = make_float4(0.f, 0.f, 0.f, 0.f);

    const int nt = KP / 16;

    #define PREF(kt_, buf_) do {                                       \
        size_t off = (size_t)(kt_) * 16;                                \
        uint32_t d0 = smb + ((buf_) * 4 * PLANE + sidx) * 4;            \
        cp16(d0,              pAh + off); cp16(d0 + 16,             pAh + off + 4); \
        cp16(d0 + PLANE*4,    pAl + off); cp16(d0 + PLANE*4 + 16,   pAl + off + 4); \
        cp16(d0 + 2*PLANE*4,  pBh + off); cp16(d0 + 2*PLANE*4 + 16, pBh + off + 4); \
        cp16(d0 + 3*PLANE*4,  pBl + off); cp16(d0 + 3*PLANE*4 + 16, pBl + off + 4); \
    } while (0)

    PREF(0, 0);
    cp_commit();

    for (int kt = 0; kt < nt; kt++) {
        cp_wait0();
        __syncthreads();
        if (kt + 1 < nt) { PREF(kt + 1, (kt + 1) & 1); cp_commit(); }

        const uint32_t base = smb + ((kt & 1) * 4 * PLANE) * 4;
        #pragma unroll
        for (int s = 0; s < 2; s++) {
            uint32_t ah0[4], ah1[4], al0[4], al1[4];
            ldsm4(ah0, base + aoff[0] + s*32);
            ldsm4(ah1, base + aoff[1] + s*32);
            ldsm4(al0, base + PLANE*4 + aoff[0] + s*32);
            ldsm4(al1, base + PLANE*4 + aoff[1] + s*32);
            #pragma unroll
            for (int p = 0; p < 4; p++) {
                uint32_t bh[4], bl[4];
                ldsm4(bh, base + 2*PLANE*4 + boff[p] + s*32);
                ldsm4(bl, base + 3*PLANE*4 + boff[p] + s*32);
                mma_x3(acc[0][2*p],   ah0, al0, bh[0], bh[1], bl[0], bl[1]);
                mma_x3(acc[0][2*p+1], ah0, al0, bh[2], bh[3], bl[2], bl[3]);
                mma_x3(acc[1][2*p],   ah1, al1, bh[0], bh[1], bl[0], bl[1]);
                mma_x3(acc[1][2*p+1], ah1, al1, bh[2], bh[3], bl[2], bl[3]);
            }
        }
    }
    #undef PREF
    __syncthreads();

    const float s0 = d_invs[0], s1 = d_invs[1];
    float* smf = (float*)smg;

    #pragma unroll
    for (int mf = 0; mf < 2; mf++) {
        int rl = wm + mf * 16 + g;
        int row = bm + rl;
        #pragma unroll
        for (int nf = 0; nf < 8; nf++) {
            int coln = wn + nf * 8 + 2 * tg;
            float4 c = acc[mf][nf];
            if (coln < 64) {
                int colp = nf * 4 + tg;
                uint32_t h0, l0, h1, l1;
                split2h(c.x * s0, c.y * s0, h0, l0);
                split2h(c.z * s0, c.w * s0, h1, l1);
                oph[(size_t)row * 32 + colp]       = h0;
                opl[(size_t)row * 32 + colp]       = l0;
                oph[(size_t)(row + 8) * 32 + colp] = h1;
                opl[(size_t)(row + 8) * 32 + colp] = l1;
            } else {
                int col = coln - 64;
                smf[rl * 68 + col]           = c.x * s1;
                smf[rl * 68 + col + 1]       = c.y * s1;
                smf[(rl + 8) * 68 + col]     = c.z * s1;
                smf[(rl + 8) * 68 + col + 1] = c.w * s1;
            }
        }
    }
    __syncthreads();

    {
        int b  = blockIdx.y >> 5;
        int h2 = blockIdx.y & 31;
        #pragma unroll
        for (int i = 0; i < 4; i++) {
            int idx = t * 4 + i;
            int w2 = idx >> 5, cp = idx & 31;
            int c0 = cp * 2;
            int r0 = 2 * w2;
            float a0 = fmaxf(fmaxf(smf[r0*68 + c0],      smf[(r0+1)*68 + c0]),
                             fmaxf(smf[(r0+64)*68 + c0], smf[(r0+65)*68 + c0]));
            float a1 = fmaxf(fmaxf(smf[r0*68 + c0+1],      smf[(r0+1)*68 + c0+1]),
                             fmaxf(smf[(r0+64)*68 + c0+1], smf[(r0+65)*68 + c0+1]));
            uint32_t h, l; split2h(a0, a1, h, l);
            size_t o = ((size_t)b * 1024 + h2 * 32 + w2) * 32 + cp;
            phh[o] = h; phl[o] = l;
        }
    }
}

// ---------------------------------------------------------------------------
// fp16 x1 GEMM: 128x128 tile (unchanged)
// ---------------------------------------------------------------------------
#define G1BUF 5120
#define GEMM1_SMEM 69632

template<int MODE>
__global__ __launch_bounds__(256, 2)
void gemm1(const uint32_t* __restrict__ Ah, const uint32_t* __restrict__ Bh,
           float* __restrict__ of, uint32_t* __restrict__ gTf,
           const float* __restrict__ X, const float* __restrict__ sigma_ptr,
           int N, int KP)
{
    extern __shared__ uint32_t smg[];
    const uint32_t smb = (uint32_t)__cvta_generic_to_shared(smg);

    const int bm = blockIdx.y * 128;
    const int bn = blockIdx.x * 128;
    const int t = threadIdx.x;
    const int warp = t >> 5, lane = t & 31, g = lane >> 2, tg = lane & 3;
    const int wm = (warp >> 1) * 32, wn = (warp & 1) * 64;

    const int ar = (lane & 7) + ((lane >> 3) & 1) * 8;
    const int ak = (lane >> 4) * 4;
    const int br = (lane & 7) + (lane >> 4) * 8;
    const int bk = ((lane >> 3) & 1) * 4;
    uint32_t aoff[2], boff[4];
    #pragma unroll
    for (int mf = 0; mf < 2; mf++) aoff[mf] = ((wm + mf*16 + ar) * 20 + ak) * 4;
    #pragma unroll
    for (int p = 0; p < 4; p++)    boff[p]  = ((2560 + (wn + p*16 + br) * 20 + bk)) * 4;

    const int rs = t >> 1, hf = (t & 1) * 8;
    const uint32_t* pA = Ah + (size_t)(bm + rs) * KP + hf;
    const uint32_t* pB = Bh + (size_t)(bn + rs) * KP + hf;
    const uint32_t sA = (rs * 20 + hf) * 4;
    const uint32_t sB = (2560 + rs * 20 + hf) * 4;

    float4 acc[2][8];
    #pragma unroll
    for (int i = 0; i < 2; i++)
        #pragma unroll
        for (int j = 0; j < 8; j++) acc[i][j] = make_float4(0.f, 0.f, 0.f, 0.f);

    const int nt = KP / 16;

    #define PREF1(kt_, buf_) do {                                   \
        size_t off = (size_t)(kt_) * 16;                             \
        uint32_t da = smb + (buf_) * G1BUF * 4 + sA;                 \
        cp16(da, pA + off); cp16(da + 16, pA + off + 4);             \
        uint32_t db = smb + (buf_) * G1BUF * 4 + sB;                 \
        cp16(db, pB + off); cp16(db + 16, pB + off + 4);             \
    } while (0)

    PREF1(0, 0); cp_commit();
    PREF1(1, 1); cp_commit();

    for (int kt = 0; kt < nt; kt++) {
        if (kt == nt - 1) cp_wait0(); else cp_wait1();
        __syncthreads();
        if (kt + 2 < nt) { PREF1(kt + 2, (kt + 2) % 3); cp_commit(); }

        const uint32_t base = smb + ((kt % 3) * G1BUF) * 4;
        #pragma unroll
        for (int s = 0; s < 2; s++) {
            uint32_t a0[4], a1[4];
            ldsm4(a0, base + aoff[0] + s*32);
            ldsm4(a1, base + aoff[1] + s*32);
            #pragma unroll
            for (int p = 0; p < 4; p++) {
                uint32_t bf[4];
                ldsm4(bf, base + boff[p] + s*32);
                mma_f16(acc[0][2*p],   a0[0], a0[1], a0[2], a0[3], bf[0], bf[1]);
                mma_f16(acc[0][2*p+1], a0[0], a0[1], a0[2], a0[3], bf[2], bf[3]);
                mma_f16(acc[1][2*p],   a1[0], a1[1], a1[2], a1[3], bf[0], bf[1]);
                mma_f16(acc[1][2*p+1], a1[0], a1[1], a1[2], a1[3], bf[2], bf[3]);
            }
        }
    }
    #undef PREF1

    const float s0 = (MODE == 1) ? d_invs[2] : d_invs[3] * __ldg(sigma_ptr);

    if (MODE == 1) {
        __syncthreads();
        float* smf = (float*)smg;
        #pragma unroll
        for (int mf = 0; mf < 2; mf++) {
            int rl = wm + mf * 16 + g;
            #pragma unroll
            for (int nf = 0; nf < 8; nf++) {
                int col = wn + nf * 8 + 2 * tg;
                float4 c = acc[mf][nf];
                smf[rl * 132 + col]           = c.x * s0;
                smf[rl * 132 + col + 1]       = c.y * s0;
                smf[(rl + 8) * 132 + col]     = c.z * s0;
                smf[(rl + 8) * 132 + col + 1] = c.w * s0;
            }
        }
        __syncthreads();
        int b  = blockIdx.y >> 5;
        int h2 = blockIdx.y & 31;
        #pragma unroll
        for (int i = 0; i < 8; i++) {
            int idx = t * 8 + i;
            int c = idx >> 4, w2p = idx & 15;
            int r0 = 4 * w2p;
            float p0 = fmaxf(fmaxf(smf[r0*132 + c],      smf[(r0+1)*132 + c]),
                             fmaxf(smf[(r0+64)*132 + c], smf[(r0+65)*132 + c]));
            float p1 = fmaxf(fmaxf(smf[(r0+2)*132 + c],  smf[(r0+3)*132 + c]),
                             fmaxf(smf[(r0+66)*132 + c], smf[(r0+67)*132 + c]));
            gTf[((size_t)b * 256 + bn + c) * 512 + h2 * 16 + w2p] = pack2h(p0, p1);
        }
    } else {
        #pragma unroll
        for (int mf = 0; mf < 2; mf++) {
            int row = bm + wm + mf * 16 + g;
            #pragma unroll
            for (int nf = 0; nf < 8; nf++) {
                int col = bn + wn + nf * 8 + 2 * tg;
                float4 c = acc[mf][nf];
                size_t i0 = (size_t)row * N + col;
                size_t i1 = (size_t)(row + 8) * N + col;
                float2 x0 = *(const float2*)&X[i0];
                float2 x1 = *(const float2*)&X[i1];
                *(float2*)&of[i0] = make_float2(x0.x + s0 * c.x, x0.y + s0 * c.y);
                *(float2*)&of[i1] = make_float2(x1.x + s0 * c.z, x1.y + s0 * c.w);
            }
        }
    }
}

// ---------------------------------------------------------------------------
// attn5: 32 q-rows/block, 256 threads (8 warps), 2 CTAs/SM.
// PSTR = 516 u32 (2064 B, 16B-aligned rows for ldmatrix — the r15 fix).
// smem: P 32x516 | mc 32x64 f32 | inv 32 | staging 2x5120 = 115,328 B
// ---------------------------------------------------------------------------
#define A5_PSTR 516
#define A5_MC   (32 * A5_PSTR)          // 16512
#define A5_INV  (A5_MC + 2048)          // 18560
#define A5_SOFF (A5_INV + 32)           // 18592
#define A5_BUF  5120
#define ATTN_SMEM ((A5_SOFF + 2 * A5_BUF) * 4)   // 115328 B

__global__ __launch_bounds__(256, 2)
void attn5(const uint32_t* __restrict__ th_h, const uint32_t* __restrict__ th_l,
           const uint32_t* __restrict__ ph_h, const uint32_t* __restrict__ ph_l,
           const uint32_t* __restrict__ gT_f,
           uint32_t* __restrict__ ag_f)
{
    extern __shared__ uint32_t sma[];
    const uint32_t smb = (uint32_t)__cvta_generic_to_shared(sma);

    const int b  = blockIdx.y;
    const int n0 = blockIdx.x * 32;
    const int t  = threadIdx.x;
    const int warp = t >> 5, lane = t & 31;
    const int g_ = lane >> 2, tg = lane & 3;
    const int mw = warp >> 2;          // 0..1: row group of 16
    const int nw = warp & 3;           // 0..3: col quarter
    const int rows0 = mw * 16;

    const int ar = (lane & 7) + ((lane >> 3) & 1) * 8;
    const int ak = (lane >> 4) * 4;
    const int br = (lane & 7) + (lane >> 4) * 8;
    const int bk = ((lane >> 3) & 1) * 4;

    // ---- stage q in staging buf 0 (32 rows x 32 u32, hi + lo) ----
    {
        int row = t >> 3, off = (t & 7) * 4;
        size_t src = ((size_t)b * LOC + n0 + row) * 32 + off;
        *(uint4*)&sma[A5_SOFF + row * 36 + off]        = *(const uint4*)&th_h[src];
        *(uint4*)&sma[A5_SOFF + 1152 + row * 36 + off] = *(const uint4*)&th_l[src];
    }
    __syncthreads();
    uint32_t qh[4][4], ql[4][4];
    {
        uint32_t qoff = smb + (A5_SOFF + (rows0 + ar) * 36 + ak) * 4;
        #pragma unroll
        for (int s = 0; s < 4; s++) ldsm4(qh[s], qoff + s*32);
        #pragma unroll
        for (int s = 0; s < 4; s++) ldsm4(ql[s], qoff + 1152*4 + s*32);
    }
    __syncthreads();

    // ---- scores: 16 chunks of 64 phi rows ----
    const int srow = t >> 2, shalf = (t & 3) * 8;
    #define PREFS(mb_, buf_) do {                                              \
        size_t src = ((size_t)b * DOWN + (mb_) + srow) * 32 + shalf;           \
        uint32_t d = smb + (A5_SOFF + (buf_) * A5_BUF + srow * 36 + shalf) * 4; \
        cp16(d,      ph_h + src);      cp16(d + 16, ph_h + src + 4);           \
        uint32_t dl = d + 2304 * 4;                                            \
        cp16(dl,     ph_l + src);      cp16(dl + 16, ph_l + src + 4);          \
    } while (0)

    PREFS(0, 0);
    cp_commit();

    for (int c = 0; c < 16; c++) {
        cp_wait0();
        __syncthreads();
        if (c + 1 < 16) { PREFS((c + 1) * 64, (c + 1) & 1); cp_commit(); }

        const uint32_t bb = smb + (A5_SOFF + (c & 1) * A5_BUF) * 4;
        float4 sc[2];
        sc[0] = make_float4(0.f, 0.f, 0.f, 0.f);
        sc[1] = make_float4(0.f, 0.f, 0.f, 0.f);

        const uint32_t boffb = ((nw * 16 + br) * 36 + bk) * 4;
        #pragma unroll
        for (int s = 0; s < 4; s++) {
            uint32_t bh[4], bl[4];
            ldsm4(bh, bb + boffb + s*32);
            ldsm4(bl, bb + 2304*4 + boffb + s*32);
            mma_x3(sc[0], qh[s], ql[s], bh[0], bh[1], bl[0], bl[1]);
            mma_x3(sc[1], qh[s], ql[s], bh[2], bh[3], bl[2], bl[3]);
        }

        float m0 = fmaxf(fmaxf(sc[0].x, sc[0].y), fmaxf(sc[1].x, sc[1].y));
        float m1 = fmaxf(fmaxf(sc[0].z, sc[0].w), fmaxf(sc[1].z, sc[1].w));
        m0 = fmaxf(m0, __shfl_xor_sync(0xffffffffu, m0, 1));
        m0 = fmaxf(m0, __shfl_xor_sync(0xffffffffu, m0, 2));
        m1 = fmaxf(m1, __shfl_xor_sync(0xffffffffu, m1, 1));
        m1 = fmaxf(m1, __shfl_xor_sync(0xffffffffu, m1, 2));
        if (tg == 0) {
            ((float*)sma)[A5_MC + (rows0 + g_) * 64 + c*4 + nw]     = m0;
            ((float*)sma)[A5_MC + (rows0 + 8 + g_) * 64 + c*4 + nw] = m1;
        }
        #pragma unroll
        for (int nf = 0; nf < 2; nf++) {
            int pairidx = c*32 + nw*8 + nf*4 + tg;
            float4 v = sc[nf];
            sma[(rows0 + g_) * A5_PSTR + pairidx]     = pack2h(__expf(v.x - m0), __expf(v.y - m0));
            sma[(rows0 + 8 + g_) * A5_PSTR + pairidx] = pack2h(__expf(v.z - m1), __expf(v.w - m1));
        }
    }
    #undef PREFS

    // prefetch first PV g-chunk (k32): [256 ch][16 u32], stride 20
    #define PREFG(kb_, buf_) do {                                              \
        size_t src = ((size_t)b * 256 + t) * 512 + ((kb_) >> 1);               \
        uint32_t d = smb + (A5_SOFF + (buf_) * A5_BUF + t * 20) * 4;           \
        cp16(d,      gT_f + src);      cp16(d + 16, gT_f + src + 4);           \
        cp16(d + 32, gT_f + src + 8);  cp16(d + 48, gT_f + src + 12);          \
    } while (0)
    PREFG(0, 0);
    cp_commit();
    __syncthreads();   // P + mc visible

    // ---- rescale: P *= exp(m_cq - m_final); row sums -> inv ----
    {
        int r = t >> 3, l8 = t & 7;
        const float* mc = (const float*)sma + A5_MC + r * 64;
        float mf = -1e30f;
        #pragma unroll
        for (int i = 0; i < 64; i++) mf = fmaxf(mf, mc[i]);
        float sum = 0.f;
        #pragma unroll 8
        for (int grp = 0; grp < 64; grp++) {
            float f = __expf(mc[grp] - mf);
            int j = grp * 8 + l8;
            uint32_t u = sma[r * A5_PSTR + j];
            __half2 h = *(__half2*)&u;
            float f0 = __half2float(h.x) * f;
            float f1 = __half2float(h.y) * f;
            sum += f0 + f1;
            sma[r * A5_PSTR + j] = pack2h(f0, f1);
        }
        sum += __shfl_xor_sync(0xffffffffu, sum, 1);
        sum += __shfl_xor_sync(0xffffffffu, sum, 2);
        sum += __shfl_xor_sync(0xffffffffu, sum, 4);
        if (l8 == 0) ((float*)sma)[A5_INV + r] = 1.0f / sum;
    }
    __syncthreads();

    // ---- PV (fp16 x1): out[32][256], 32 chunks of k32, warp tile 16x64 ----
    const int wn2 = nw * 64;
    const uint32_t poff = ((rows0 + ar) * A5_PSTR + ak) * 4;
    float4 oc[8];
    #pragma unroll
    for (int nf = 0; nf < 8; nf++) oc[nf] = make_float4(0.f, 0.f, 0.f, 0.f);

    for (int ki = 0; ki < 32; ki++) {
        cp_wait0();
        __syncthreads();
        if (ki + 1 < 32) { PREFG((ki + 1) * 32, (ki + 1) & 1); cp_commit(); }

        const uint32_t bb = smb + (A5_SOFF + (ki & 1) * A5_BUF) * 4;
        #pragma unroll
        for (int s = 0; s < 2; s++) {
            uint32_t a[4];
            ldsm4(a, smb + poff + (ki * 16 + s * 8) * 4);
            #pragma unroll
            for (int p = 0; p < 4; p++) {
                uint32_t boffg = ((wn2 + p * 16 + br) * 20 + bk) * 4;
                uint32_t bg[4];
                ldsm4(bg, bb + boffg + s*32);
                mma_f16(oc[2*p],   a[0], a[1], a[2], a[3], bg[0], bg[1]);
                mma_f16(oc[2*p+1], a[0], a[1], a[2], a[3], bg[2], bg[3]);
            }
        }
    }
    #undef PREFG

    const float i0 = ((const float*)sma)[A5_INV + rows0 + g_];
    const float i1 = ((const float*)sma)[A5_INV + rows0 + 8 + g_];
    #pragma unroll
    for (int nf = 0; nf < 8; nf++) {
        int colp = wn2 / 2 + nf * 4 + tg;
        size_t r0 = ((size_t)b * LOC + n0 + rows0 + g_) * 128 + colp;
        size_t r1 = ((size_t)b * LOC + n0 + rows0 + 8 + g_) * 128 + colp;
        ag_f[r0] = pack2h(oc[nf].x * i0, oc[nf].y * i0);
        ag_f[r1] = pack2h(oc[nf].z * i1, oc[nf].w * i1);
    }
}

// ---------------------------------------------------------------------------
// kernel_launch
// ---------------------------------------------------------------------------
extern "C" void kernel_launch(void* const* d_in, const int* in_sizes, int n_in,
                              void* d_out, int out_size)
{
    const float* x       = (const float*)d_in[0];
    const float* k_theta = (const float*)d_in[1];
    const float* u_theta = (const float*)d_in[2];
    const float* k_phi   = (const float*)d_in[3];
    const float* u_phi   = (const float*)d_in[4];
    const float* k_g     = (const float*)d_in[5];
    const float* u_g     = (const float*)d_in[6];
    const float* k_attn  = (const float*)d_in[7];
    const float* u_attn  = (const float*)d_in[8];
    const float* sigma   = (const float*)d_in[9];
    float* out = (float*)d_out;

    uint32_t *xh, *xl, *wtpTh, *wtpTl, *wgTf, *waTf;
    uint32_t *thh, *thl, *phh, *phl, *gTf, *agf;
    cudaGetSymbolAddress((void**)&xh,    d_xh);
    cudaGetSymbolAddress((void**)&xl,    d_xl);
    cudaGetSymbolAddress((void**)&wtpTh, d_wtpTh);
    cudaGetSymbolAddress((void**)&wtpTl, d_wtpTl);
    cudaGetSymbolAddress((void**)&wgTf,  d_wgTf);
    cudaGetSymbolAddress((void**)&waTf,  d_waTf);
    cudaGetSymbolAddress((void**)&thh,   d_thh);
    cudaGetSymbolAddress((void**)&thl,   d_thl);
    cudaGetSymbolAddress((void**)&phh,   d_phh);
    cudaGetSymbolAddress((void**)&phl,   d_phl);
    cudaGetSymbolAddress((void**)&gTf,   d_gTf);
    cudaGetSymbolAddress((void**)&agf,   d_agf);

    cudaFuncSetAttribute(gemm_x3,  cudaFuncAttributeMaxDynamicSharedMemorySize, GEMM_SMEM);
    cudaFuncSetAttribute(gemm1<1>, cudaFuncAttributeMaxDynamicSharedMemorySize, GEMM1_SMEM);
    cudaFuncSetAttribute(gemm1<2>, cudaFuncAttributeMaxDynamicSharedMemorySize, GEMM1_SMEM);
    cudaFuncSetAttribute(attn5,    cudaFuncAttributeMaxDynamicSharedMemorySize, ATTN_SMEM);

    prep_all<<<17028, 256>>>(x, k_theta, u_theta, k_phi, u_phi,
                             k_g, u_g, k_attn, u_attn,
                             xh, xl, wtpTh, wtpTl, wgTf, waTf);
    gemm_x3<<<dim3(1, MTOT / 128), 256, GEMM_SMEM>>>(
        xh, xl, wtpTh, wtpTl, thh, thl, phh, phl, 256);
    gemm1<1><<<dim3(2, MTOT / 128), 256, GEMM1_SMEM>>>(
        xh, wgTf, nullptr, gTf, nullptr, nullptr, 256, 256);
    attn5<<<dim3(LOC / 32, B_), 256, ATTN_SMEM>>>(thh, thl, phh, phl, gTf, agf);
    gemm1<2><<<dim3(4, MTOT / 128), 256, GEMM1_SMEM>>>(
        agf, waTf, out, nullptr, x, sigma, 512, 128);
}